// round 13
// baseline (speedup 1.0000x reference)
#include <cuda_runtime.h>
#include <cuda_fp16.h>
#include <math.h>

// ---------------------------------------------------------------------------
// Fused 3-layer GCN, fixed 21-node hand skeleton, 50000 graphs.
// R13 = R12 with barriers narrowed to independent half-groups:
//   warps 0-3 (graphs 0-3) and warps 4-7 (graphs 4-7) share NO shared-memory
//   state after staging -> both per-tile barriers become 128-thread named
//   barriers (bar.sync 1+half). Two de-correlated pipelines per CTA.
//   Everything else identical to R12 (MMA pool + movmatrix-fused layer 3).
// ---------------------------------------------------------------------------

#define NODES   21
#define NCLS    29
#define NTILES  6250          // 50000 / 8
#define GRID    444           // 148 SM x 3 CTA
#define R2C     0.70710678118654752440f
#define WROOT   4.535533905932737f

// ---- smem byte offsets ----------------------------------------------------
#define SB_H    0             // h1mix fp16 [192 rows][128B] swizzled  24576
#define SB_A    24576         // W2'*s2 fp16 [128 j][128B] swizzled    16384
#define SB_BP   40960         // pool B [12 nt][8 n][8 k] fp16         1536
#define SB_W3F  42496         // W3^T/21 frag order [4 jq][2 ks][2 mt][32][16B]
#define SB_PY   50688         // partial y [4 jq][2 half][4 gl][32] f32 4096
#define SB_X    54784         // x staged [8 w][21][4] f32             2688
#define SB_T2   57472         // 128 f32
#define SB_B3   57984         // 32 f32
#define SB_C    58112         // W1 [3][64] f32                        768
#define SB_S1   58880         // s1 half2 [32]                         128
#define SB_T1   59008         // t1 half2 [32]                         128
#define SB_TOT  59136         // x3 CTA = 177,408

// ---- PTX helpers ----------------------------------------------------------
__device__ __forceinline__ unsigned smem_u32(const void* p) {
    unsigned a;
    asm("{ .reg .u64 t; cvta.to.shared.u64 t, %1; cvt.u32.u64 %0, t; }"
        : "=r"(a) : "l"(p));
    return a;
}
__device__ __forceinline__ void ldsm4(unsigned& r0, unsigned& r1,
                                      unsigned& r2, unsigned& r3, unsigned a) {
    asm volatile("ldmatrix.sync.aligned.m8n8.x4.shared.b16 {%0,%1,%2,%3}, [%4];"
                 : "=r"(r0), "=r"(r1), "=r"(r2), "=r"(r3) : "r"(a));
}
__device__ __forceinline__ void ldsm1(unsigned& r0, unsigned a) {
    asm volatile("ldmatrix.sync.aligned.m8n8.x1.shared.b16 {%0}, [%1];"
                 : "=r"(r0) : "r"(a));
}
__device__ __forceinline__ unsigned movm(unsigned a) {
    unsigned d;
    asm volatile("movmatrix.sync.aligned.m8n8.trans.b16 %0, %1;"
                 : "=r"(d) : "r"(a));
    return d;
}
__device__ __forceinline__ void mma16816(float* c, const unsigned* a,
                                         unsigned b0, unsigned b1) {
    asm volatile(
        "mma.sync.aligned.m16n8k16.row.col.f32.f16.f16.f32 "
        "{%0,%1,%2,%3}, {%4,%5,%6,%7}, {%8,%9}, {%0,%1,%2,%3};"
        : "+f"(c[0]), "+f"(c[1]), "+f"(c[2]), "+f"(c[3])
        : "r"(a[0]), "r"(a[1]), "r"(a[2]), "r"(a[3]), "r"(b0), "r"(b1));
}
__device__ __forceinline__ void mma16808(float* c, unsigned a0, unsigned a1,
                                         unsigned b0) {
    asm volatile(
        "mma.sync.aligned.m16n8k8.row.col.f32.f16.f16.f32 "
        "{%0,%1,%2,%3}, {%4,%5}, {%6}, {%0,%1,%2,%3};"
        : "+f"(c[0]), "+f"(c[1]), "+f"(c[2]), "+f"(c[3])
        : "r"(a0), "r"(a1), "r"(b0));
}
__device__ __forceinline__ void barh(int half) {   // half-group barrier
    asm volatile("bar.sync %0, 128;" :: "r"(1 + half) : "memory");
}
__device__ __forceinline__ unsigned relupack2(float a, float b, __half2 t) {
    __half2 h = __floats2half2_rn(a, b);
    h = __hmax2(__hadd2(h, t), __float2half2_rn(0.f));
    return *(unsigned*)&h;
}
__device__ __forceinline__ float wraw(int l) {      // raw pooled node weight
    if (l == 0)  return WROOT;
    if (l >= 21) return 0.f;
    return ((l & 3) == 0) ? 0.5f : 1.0f;
}

// ---------------------------------------------------------------------------
__global__ void __launch_bounds__(256, 3)
gcn_r13_kernel(const float* __restrict__ x,
               const float* __restrict__ W1, const float* __restrict__ b1,
               const float* __restrict__ g1, const float* __restrict__ be1,
               const float* __restrict__ m1, const float* __restrict__ v1,
               const float* __restrict__ W2, const float* __restrict__ b2,
               const float* __restrict__ g2, const float* __restrict__ be2,
               const float* __restrict__ m2, const float* __restrict__ v2,
               const float* __restrict__ W3, const float* __restrict__ b3,
               float* __restrict__ out) {
    extern __shared__ char smc[];
    float* smf = (float*)smc;
    const unsigned sb = smem_u32(smc);
    const int tid  = threadIdx.x;
    const int lane = tid & 31;
    const int wid  = tid >> 5;          // 0..7
    const int jq   = wid & 3;           // j-strip of 32
    const int half = wid >> 2;          // 0: graphs 0-3, 1: graphs 4-7
    const int lr   = lane >> 2;         // fragment row
    const int lc   = lane & 3;          // fragment col-pair

    // ---------------- staging (once per CTA) -------------------------------
    for (int i = tid; i < 8192; i += 256) {          // A = W2^T*diag(s2), swz
        int j = i & 127, k = i >> 7;
        float s = g2[j] * rsqrtf(v2[j] + 1e-5f);
        int off = SB_A + j * 128 + (((k >> 3) ^ (j & 7)) << 4) + (k & 7) * 2;
        *(__half*)(smc + off) = __float2half(W2[k * 128 + j] * s);
    }
    for (int i = tid; i < 768; i += 256) {           // pool B [nt][n][k]
        int nt = i >> 6, n = (i >> 3) & 7, k = i & 7;
        int col = 8 * nt + k;
        int gl = col / 24, ln = col % 24;
        float v_ = (n == gl) ? wraw(ln) : 0.f;
        *(__half*)(smc + SB_BP + nt * 128 + n * 16 + k * 2) = __float2half(v_);
    }
    // W3^T/21 in A-fragment order: [jq][ks][mt][lane][q] half2
    for (int i = tid; i < 4096; i += 256) {
        int q   = i & 3;
        int ln  = (i >> 2) & 31;
        int mt  = (i >> 7) & 1;
        int ks  = (i >> 8) & 1;
        int jq_ = (i >> 9) & 3;
        int lr_ = ln >> 2, lc_ = ln & 3;
        int cls = 16 * mt + lr_ + 8 * (q & 1);
        int jj  = 32 * jq_ + 16 * ks + 2 * lc_ + 8 * (q >> 1);
        float f0 = (cls < NCLS) ? W3[jj * NCLS + cls] / 21.f : 0.f;
        float f1 = (cls < NCLS) ? W3[(jj + 1) * NCLS + cls] / 21.f : 0.f;
        ((__half2*)(smc + SB_W3F))[i] = __floats2half2_rn(f0, f1);
    }
    for (int i = tid; i < 768; i += 256) {           // zero H pad rows n=21..23
        int g = i / 96, rem = i % 96;
        int row = 24 * g + 21 + rem / 32;
        *(float*)(smc + SB_H + row * 128 + (rem % 32) * 4) = 0.f;
    }
    if (tid < 128) {
        float s = g2[tid] * rsqrtf(v2[tid] + 1e-5f);
        smf[SB_T2 / 4 + tid] = (b2[tid] - m2[tid]) * s + be2[tid];
    }
    if (tid < NCLS) smf[SB_B3 / 4 + tid] = b3[tid];
    for (int i = tid; i < 192; i += 256) smf[SB_C / 4 + i] = W1[i];
    if (tid < 32) {                                  // s1/t1 as half2 pairs
        int c2 = 2 * tid;
        float sa = g1[c2] * rsqrtf(v1[c2] + 1e-5f);
        float sbv = g1[c2 + 1] * rsqrtf(v1[c2 + 1] + 1e-5f);
        float ta = (b1[c2] - m1[c2]) * sa + be1[c2];
        float tb = (b1[c2 + 1] - m1[c2 + 1]) * sbv + be1[c2 + 1];
        ((__half2*)(smc + SB_S1))[tid] = __floats2half2_rn(sa, sbv);
        ((__half2*)(smc + SB_T1))[tid] = __floats2half2_rn(ta, tb);
    }
    __syncthreads();                                 // staging fence (once)

    // ---- per-warp invariants ---------------------------------------------
    __half2 t2h[4];
    #pragma unroll
    for (int r = 0; r < 4; ++r)
        t2h[r] = __float2half2_rn(smf[SB_T2 / 4 + 32 * jq + lr + 8 * r]);
    unsigned bB[2];
    #pragma unroll
    for (int c = 0; c < 2; ++c)
        bB[c] = sb + SB_H + (96 * half + (lane & 7)) * 128
              + ((((lane >> 3) + 4 * c) ^ (lane & 7)) << 4);
    const unsigned bpAddr = sb + SB_BP + (lane & 7) * 16;
    float* const px = smf + SB_X / 4 + wid * 84;     // [21][4] per warp

    // main-GEMM A fragments (static W2 strip): load ONCE (32 regs)
    unsigned ah[4][2][4];
    #pragma unroll
    for (int kk = 0; kk < 4; ++kk)
        #pragma unroll
        for (int mt = 0; mt < 2; ++mt) {
            int row = 32 * jq + 16 * mt + (lane & 15);
            ldsm4(ah[kk][mt][0], ah[kk][mt][1], ah[kk][mt][2], ah[kk][mt][3],
                  sb + SB_A + row * 128
                  + ((((lane >> 4) + 2 * kk) ^ (row & 7)) << 4));
        }

    for (int tile = blockIdx.x; tile < NTILES; tile += GRID) {
        const int gbase = tile * 8;

        // ---- phase 1: layer 1 + mix + BN + ReLU + mix2 -> H (warp=graph) --
        {
            const float2 w1a = ((const float2*)(smf + SB_C / 4))[lane];
            const float2 w1b = ((const float2*)(smf + SB_C / 4 + 64))[lane];
            const float2 w1c = ((const float2*)(smf + SB_C / 4 + 128))[lane];
            const __half2 s1h = ((const __half2*)(smc + SB_S1))[lane];
            const __half2 t1h = ((const __half2*)(smc + SB_T1))[lane];
            const __half2 h05 = __float2half2_rn(0.5f);
            const __half2 hR2 = __float2half2_rn(R2C);
            const __half2 hz  = __float2half2_rn(0.f);
            const float* xg = x + (size_t)(gbase + wid) * 63;

            // stage x into per-warp padded buffer, then broadcast via LDS
            {
                float xa0 = xg[lane];
                px[(lane / 3) * 4 + lane % 3] = xa0;
                if (lane < 31) {
                    float xa1 = xg[32 + lane];
                    int p1 = 32 + lane;
                    px[(p1 / 3) * 4 + p1 % 3] = xa1;
                }
            }
            __syncwarp();

            const int rb = 24 * wid;
            const int c4 = lane >> 2;
            const int lo = (lane & 3) * 4;

            __half2 z02, h02;
            {
                float4 xq = *(const float4*)(px);
                float zx = fmaf(xq.x, w1a.x, fmaf(xq.y, w1b.x, xq.z * w1c.x));
                float zy = fmaf(xq.x, w1a.y, fmaf(xq.y, w1b.y, xq.z * w1c.y));
                z02 = __floats2half2_rn(zx, zy);
                h02 = __hmax2(__hfma2(z02, s1h, t1h), hz);
                *(__half2*)(smc + SB_H + rb * 128 + ((c4 ^ (rb & 7)) << 4) + lo)
                    = h02;
            }
            #pragma unroll
            for (int f = 0; f < 5; ++f) {
                __half2 zp2 = z02, hp2 = h02;
                #pragma unroll
                for (int i = 0; i < 4; ++i) {
                    const int n = 1 + 4 * f + i;
                    const __half2 cph = (i == 0) ? hR2 : h05;
                    float4 xq = *(const float4*)(px + 4 * n);
                    float zx = fmaf(xq.x, w1a.x, fmaf(xq.y, w1b.x, xq.z * w1c.x));
                    float zy = fmaf(xq.x, w1a.y, fmaf(xq.y, w1b.y, xq.z * w1c.y));
                    __half2 zn2 = __floats2half2_rn(zx, zy);
                    __half2 m12 = __hfma2(zn2, h05, __hmul2(zp2, cph));
                    __half2 hn2 = __hmax2(__hfma2(m12, s1h, t1h), hz);
                    __half2 m22 = __hfma2(hn2, h05, __hmul2(hp2, cph));
                    const int row = rb + n;
                    *(__half2*)(smc + SB_H + row * 128
                                + ((c4 ^ (row & 7)) << 4) + lo) = m22;
                    zp2 = zn2; hp2 = hn2;
                }
            }
        }
        barh(half);                                   // BAR1: half's H ready

        // ---- phase 2: MMA + MMA pooling + fused MMA layer-3 ---------------
        {
            float vC[2][4];
            #pragma unroll
            for (int mt = 0; mt < 2; ++mt)
                #pragma unroll
                for (int q = 0; q < 4; ++q) vC[mt][q] = 0.f;

            #pragma unroll
            for (int nt = 0; nt < 12; ++nt) {
                float acc[8] = {0.f,0.f,0.f,0.f,0.f,0.f,0.f,0.f};
                unsigned b[8];
                ldsm4(b[0], b[1], b[2], b[3], bB[0] + nt * 1024);
                ldsm4(b[4], b[5], b[6], b[7], bB[1] + nt * 1024);
                #pragma unroll
                for (int kk = 0; kk < 4; ++kk) {
                    mma16816(acc,     ah[kk][0], b[2 * kk], b[2 * kk + 1]);
                    mma16816(acc + 4, ah[kk][1], b[2 * kk], b[2 * kk + 1]);
                }
                unsigned bp;
                ldsm1(bp, bpAddr + nt * 128);
                #pragma unroll
                for (int mt = 0; mt < 2; ++mt) {
                    unsigned pa0 = relupack2(acc[4 * mt], acc[4 * mt + 1],
                                             t2h[2 * mt]);
                    unsigned pa1 = relupack2(acc[4 * mt + 2], acc[4 * mt + 3],
                                             t2h[2 * mt + 1]);
                    mma16808(vC[mt], pa0, pa1, bp);
                }
            }

            // transpose vC (j x g) -> B-fragment (k=j, n=g) via movmatrix
            unsigned bT[2][2];
            #pragma unroll
            for (int mt = 0; mt < 2; ++mt) {
                __half2 p0 = __floats2half2_rn(vC[mt][0], vC[mt][1]);
                __half2 p1 = __floats2half2_rn(vC[mt][2], vC[mt][3]);
                bT[mt][0] = movm(*(unsigned*)&p0);    // j block lower 8
                bT[mt][1] = movm(*(unsigned*)&p1);    // j block upper 8
            }
            // layer-3 MMA: k = own 32 j's, A = W3^T/21 fragments from smem
            float yc[8] = {0.f,0.f,0.f,0.f,0.f,0.f,0.f,0.f};
            #pragma unroll
            for (int ks = 0; ks < 2; ++ks) {
                uint4 aw0 = *(const uint4*)(smc + SB_W3F
                            + ((jq * 2 + ks) * 2 + 0) * 512 + lane * 16);
                mma16816(yc, (const unsigned*)&aw0, bT[ks][0], bT[ks][1]);
                uint4 aw1 = *(const uint4*)(smc + SB_W3F
                            + ((jq * 2 + ks) * 2 + 1) * 512 + lane * 16);
                mma16816(yc + 4, (const unsigned*)&aw1, bT[ks][0], bT[ks][1]);
            }
            // store partial y: [jq][half][gl][32 c]; valid g-slots at lc<2
            if (lc < 2) {
                float* py = smf + SB_PY / 4 + ((jq * 2 + half) * 4) * 32;
                #pragma unroll
                for (int mt = 0; mt < 2; ++mt) {
                    py[(2 * lc)     * 32 + 16 * mt + lr]     = yc[4 * mt];
                    py[(2 * lc + 1) * 32 + 16 * mt + lr]     = yc[4 * mt + 1];
                    py[(2 * lc)     * 32 + 16 * mt + lr + 8] = yc[4 * mt + 2];
                    py[(2 * lc + 1) * 32 + 16 * mt + lr + 8] = yc[4 * mt + 3];
                }
            }
        }
        barh(half);                                   // BAR2: half's PY ready

        // ---- phase 5: combine + log_softmax (warp = graph) ----------------
        {
            float yy = smf[SB_PY / 4 + (0 * 2 + half) * 128 + (wid & 3) * 32 + lane]
                     + smf[SB_PY / 4 + (1 * 2 + half) * 128 + (wid & 3) * 32 + lane]
                     + smf[SB_PY / 4 + (2 * 2 + half) * 128 + (wid & 3) * 32 + lane]
                     + smf[SB_PY / 4 + (3 * 2 + half) * 128 + (wid & 3) * 32 + lane];
            float logit = (lane < NCLS) ? yy + smf[SB_B3 / 4 + lane] : -1e30f;
            float mx = logit;
            #pragma unroll
            for (int o = 16; o; o >>= 1)
                mx = fmaxf(mx, __shfl_xor_sync(0xffffffffu, mx, o));
            float e = (lane < NCLS) ? __expf(logit - mx) : 0.f;
            float s = e;
            #pragma unroll
            for (int o = 16; o; o >>= 1)
                s += __shfl_xor_sync(0xffffffffu, s, o);
            if (lane < NCLS)
                out[(size_t)(gbase + wid) * NCLS + lane]
                    = logit - mx - __logf(s);
        }
        // Hazards (all within a half-group): next P1's H writes ordered by
        // BAR2 + next BAR1; P5's PY reads precede next tile's P2 PY writes
        // via next BAR1. Cross-half: no shared state after staging.
    }
}

extern "C" void kernel_launch(void* const* d_in, const int* in_sizes, int n_in,
                              void* d_out, int out_size) {
    const float* x   = (const float*)d_in[0];
    const float* W1  = (const float*)d_in[1];
    const float* b1  = (const float*)d_in[2];
    const float* g1  = (const float*)d_in[3];
    const float* be1 = (const float*)d_in[4];
    const float* m1  = (const float*)d_in[5];
    const float* v1  = (const float*)d_in[6];
    const float* W2  = (const float*)d_in[7];
    const float* b2  = (const float*)d_in[8];
    const float* g2  = (const float*)d_in[9];
    const float* be2 = (const float*)d_in[10];
    const float* m2  = (const float*)d_in[11];
    const float* v2  = (const float*)d_in[12];
    const float* W3  = (const float*)d_in[13];
    const float* b3  = (const float*)d_in[14];

    cudaFuncSetAttribute(gcn_r13_kernel,
                         cudaFuncAttributeMaxDynamicSharedMemorySize, SB_TOT);
    gcn_r13_kernel<<<GRID, 256, SB_TOT>>>(
        x, W1, b1, g1, be1, m1, v1,
        W2, b2, g2, be2, m2, v2, W3, b3, (float*)d_out);
}

// round 14
// speedup vs baseline: 1.0415x; 1.0415x over previous
#include <cuda_runtime.h>
#include <cuda_fp16.h>
#include <math.h>

// ---------------------------------------------------------------------------
// Fused 3-layer GCN, fixed 21-node hand skeleton, 50000 graphs.
// R14 = R12 (best structure: MMA pooling + movmatrix-fused layer 3, block
// barriers) with the phase-1 front end converted to half2:
//   * x staged as DUPLICATED half2 (x,x); W1 as column-pair half2 constants
//   * z = 3 HFMA2 ops/node, no f32->half pack (z is born half2)
// ---------------------------------------------------------------------------

#define NODES   21
#define NCLS    29
#define NTILES  6250          // 50000 / 8
#define GRID    444           // 148 SM x 3 CTA
#define R2C     0.70710678118654752440f
#define WROOT   4.535533905932737f

// ---- smem byte offsets ----------------------------------------------------
#define SB_H    0             // h1mix fp16 [192 rows][128B] swizzled  24576
#define SB_A    24576         // W2'*s2 fp16 [128 j][128B] swizzled    16384
#define SB_BP   40960         // pool B [12 nt][8 n][8 k] fp16         1536
#define SB_W3F  42496         // W3^T/21 frag order [4 jq][2 ks][2 mt][32][16B]
#define SB_PY   50688         // partial y [4 jq][2 half][4 gl][32] f32 4096
#define SB_X    54784         // x staged dup-half2 [8 w][21][4]       2688
#define SB_T2   57472         // 128 f32
#define SB_B3   57984         // 32 f32
#define SB_C    58112         // W1 half2 col-pairs [3][32]            384(+pad)
#define SB_S1   58880         // s1 half2 [32]                         128
#define SB_T1   59008         // t1 half2 [32]                         128
#define SB_TOT  59136         // x3 CTA = 177,408

// ---- PTX helpers ----------------------------------------------------------
__device__ __forceinline__ unsigned smem_u32(const void* p) {
    unsigned a;
    asm("{ .reg .u64 t; cvta.to.shared.u64 t, %1; cvt.u32.u64 %0, t; }"
        : "=r"(a) : "l"(p));
    return a;
}
__device__ __forceinline__ void ldsm4(unsigned& r0, unsigned& r1,
                                      unsigned& r2, unsigned& r3, unsigned a) {
    asm volatile("ldmatrix.sync.aligned.m8n8.x4.shared.b16 {%0,%1,%2,%3}, [%4];"
                 : "=r"(r0), "=r"(r1), "=r"(r2), "=r"(r3) : "r"(a));
}
__device__ __forceinline__ void ldsm1(unsigned& r0, unsigned a) {
    asm volatile("ldmatrix.sync.aligned.m8n8.x1.shared.b16 {%0}, [%1];"
                 : "=r"(r0) : "r"(a));
}
__device__ __forceinline__ unsigned movm(unsigned a) {
    unsigned d;
    asm volatile("movmatrix.sync.aligned.m8n8.trans.b16 %0, %1;"
                 : "=r"(d) : "r"(a));
    return d;
}
__device__ __forceinline__ void mma16816(float* c, const unsigned* a,
                                         unsigned b0, unsigned b1) {
    asm volatile(
        "mma.sync.aligned.m16n8k16.row.col.f32.f16.f16.f32 "
        "{%0,%1,%2,%3}, {%4,%5,%6,%7}, {%8,%9}, {%0,%1,%2,%3};"
        : "+f"(c[0]), "+f"(c[1]), "+f"(c[2]), "+f"(c[3])
        : "r"(a[0]), "r"(a[1]), "r"(a[2]), "r"(a[3]), "r"(b0), "r"(b1));
}
__device__ __forceinline__ void mma16808(float* c, unsigned a0, unsigned a1,
                                         unsigned b0) {
    asm volatile(
        "mma.sync.aligned.m16n8k8.row.col.f32.f16.f16.f32 "
        "{%0,%1,%2,%3}, {%4,%5}, {%6}, {%0,%1,%2,%3};"
        : "+f"(c[0]), "+f"(c[1]), "+f"(c[2]), "+f"(c[3])
        : "r"(a0), "r"(a1), "r"(b0));
}
__device__ __forceinline__ unsigned relupack2(float a, float b, __half2 t) {
    __half2 h = __floats2half2_rn(a, b);
    h = __hmax2(__hadd2(h, t), __float2half2_rn(0.f));
    return *(unsigned*)&h;
}
__device__ __forceinline__ float wraw(int l) {      // raw pooled node weight
    if (l == 0)  return WROOT;
    if (l >= 21) return 0.f;
    return ((l & 3) == 0) ? 0.5f : 1.0f;
}

// ---------------------------------------------------------------------------
__global__ void __launch_bounds__(256, 3)
gcn_r14_kernel(const float* __restrict__ x,
               const float* __restrict__ W1, const float* __restrict__ b1,
               const float* __restrict__ g1, const float* __restrict__ be1,
               const float* __restrict__ m1, const float* __restrict__ v1,
               const float* __restrict__ W2, const float* __restrict__ b2,
               const float* __restrict__ g2, const float* __restrict__ be2,
               const float* __restrict__ m2, const float* __restrict__ v2,
               const float* __restrict__ W3, const float* __restrict__ b3,
               float* __restrict__ out) {
    extern __shared__ char smc[];
    float* smf = (float*)smc;
    const unsigned sb = smem_u32(smc);
    const int tid  = threadIdx.x;
    const int lane = tid & 31;
    const int wid  = tid >> 5;          // 0..7
    const int jq   = wid & 3;           // j-strip of 32
    const int half = wid >> 2;          // 0: graphs 0-3, 1: graphs 4-7
    const int lr   = lane >> 2;         // fragment row
    const int lc   = lane & 3;          // fragment col-pair

    // ---------------- staging (once per CTA) -------------------------------
    for (int i = tid; i < 8192; i += 256) {          // A = W2^T*diag(s2), swz
        int j = i & 127, k = i >> 7;
        float s = g2[j] * rsqrtf(v2[j] + 1e-5f);
        int off = SB_A + j * 128 + (((k >> 3) ^ (j & 7)) << 4) + (k & 7) * 2;
        *(__half*)(smc + off) = __float2half(W2[k * 128 + j] * s);
    }
    for (int i = tid; i < 768; i += 256) {           // pool B [nt][n][k]
        int nt = i >> 6, n = (i >> 3) & 7, k = i & 7;
        int col = 8 * nt + k;
        int gl = col / 24, ln = col % 24;
        float v_ = (n == gl) ? wraw(ln) : 0.f;
        *(__half*)(smc + SB_BP + nt * 128 + n * 16 + k * 2) = __float2half(v_);
    }
    // W3^T/21 in A-fragment order: [jq][ks][mt][lane][q] half2
    for (int i = tid; i < 4096; i += 256) {
        int q   = i & 3;
        int ln  = (i >> 2) & 31;
        int mt  = (i >> 7) & 1;
        int ks  = (i >> 8) & 1;
        int jq_ = (i >> 9) & 3;
        int lr_ = ln >> 2, lc_ = ln & 3;
        int cls = 16 * mt + lr_ + 8 * (q & 1);
        int jj  = 32 * jq_ + 16 * ks + 2 * lc_ + 8 * (q >> 1);
        float f0 = (cls < NCLS) ? W3[jj * NCLS + cls] / 21.f : 0.f;
        float f1 = (cls < NCLS) ? W3[(jj + 1) * NCLS + cls] / 21.f : 0.f;
        ((__half2*)(smc + SB_W3F))[i] = __floats2half2_rn(f0, f1);
    }
    for (int i = tid; i < 768; i += 256) {           // zero H pad rows n=21..23
        int g = i / 96, rem = i % 96;
        int row = 24 * g + 21 + rem / 32;
        *(float*)(smc + SB_H + row * 128 + (rem % 32) * 4) = 0.f;
    }
    if (tid < 128) {
        float s = g2[tid] * rsqrtf(v2[tid] + 1e-5f);
        smf[SB_T2 / 4 + tid] = (b2[tid] - m2[tid]) * s + be2[tid];
    }
    if (tid < NCLS) smf[SB_B3 / 4 + tid] = b3[tid];
    if (tid < 32) {                                  // W1 col-pair half2 [3][32]
        int c2 = 2 * tid;
        ((__half2*)(smc + SB_C))[tid]      = __floats2half2_rn(W1[c2],       W1[c2 + 1]);
        ((__half2*)(smc + SB_C))[32 + tid] = __floats2half2_rn(W1[64 + c2],  W1[65 + c2]);
        ((__half2*)(smc + SB_C))[64 + tid] = __floats2half2_rn(W1[128 + c2], W1[129 + c2]);
    }
    if (tid < 32) {                                  // s1/t1 as half2 pairs
        int c2 = 2 * tid;
        float sa = g1[c2] * rsqrtf(v1[c2] + 1e-5f);
        float sbv = g1[c2 + 1] * rsqrtf(v1[c2 + 1] + 1e-5f);
        float ta = (b1[c2] - m1[c2]) * sa + be1[c2];
        float tb = (b1[c2 + 1] - m1[c2 + 1]) * sbv + be1[c2 + 1];
        ((__half2*)(smc + SB_S1))[tid] = __floats2half2_rn(sa, sbv);
        ((__half2*)(smc + SB_T1))[tid] = __floats2half2_rn(ta, tb);
    }
    __syncthreads();

    // ---- per-warp invariants ---------------------------------------------
    __half2 t2h[4];
    #pragma unroll
    for (int r = 0; r < 4; ++r)
        t2h[r] = __float2half2_rn(smf[SB_T2 / 4 + 32 * jq + lr + 8 * r]);
    unsigned bB[2];
    #pragma unroll
    for (int c = 0; c < 2; ++c)
        bB[c] = sb + SB_H + (96 * half + (lane & 7)) * 128
              + ((((lane >> 3) + 4 * c) ^ (lane & 7)) << 4);
    const unsigned bpAddr = sb + SB_BP + (lane & 7) * 16;
    __half2* const px = (__half2*)(smc + SB_X) + wid * 84;  // [21][4] dup x

    // main-GEMM A fragments (static W2 strip): load ONCE (32 regs)
    unsigned ah[4][2][4];
    #pragma unroll
    for (int kk = 0; kk < 4; ++kk)
        #pragma unroll
        for (int mt = 0; mt < 2; ++mt) {
            int row = 32 * jq + 16 * mt + (lane & 15);
            ldsm4(ah[kk][mt][0], ah[kk][mt][1], ah[kk][mt][2], ah[kk][mt][3],
                  sb + SB_A + row * 128
                  + ((((lane >> 4) + 2 * kk) ^ (row & 7)) << 4));
        }

    for (int tile = blockIdx.x; tile < NTILES; tile += GRID) {
        const int gbase = tile * 8;

        // ---- phase 1: layer 1 + mix + BN + ReLU + mix2 -> H (warp=graph) --
        {
            const __half2 w1ah = ((const __half2*)(smc + SB_C))[lane];
            const __half2 w1bh = ((const __half2*)(smc + SB_C))[32 + lane];
            const __half2 w1ch = ((const __half2*)(smc + SB_C))[64 + lane];
            const __half2 s1h = ((const __half2*)(smc + SB_S1))[lane];
            const __half2 t1h = ((const __half2*)(smc + SB_T1))[lane];
            const __half2 h05 = __float2half2_rn(0.5f);
            const __half2 hR2 = __float2half2_rn(R2C);
            const __half2 hz  = __float2half2_rn(0.f);
            const float* xg = x + (size_t)(gbase + wid) * 63;

            // stage x as duplicated half2 into per-warp padded buffer
            {
                float xa0 = xg[lane];
                px[(lane / 3) * 4 + lane % 3]
                    = __half2half2(__float2half(xa0));
                if (lane < 31) {
                    float xa1 = xg[32 + lane];
                    int p1 = 32 + lane;
                    px[(p1 / 3) * 4 + p1 % 3]
                        = __half2half2(__float2half(xa1));
                }
            }
            __syncwarp();

            const int rb = 24 * wid;
            const int c4 = lane >> 2;
            const int lo = (lane & 3) * 4;

            __half2 z02, h02;
            {
                uint4 xq = *(const uint4*)(px);
                __half2 xa2 = *(__half2*)&xq.x;
                __half2 xb2 = *(__half2*)&xq.y;
                __half2 xc2 = *(__half2*)&xq.z;
                z02 = __hfma2(xa2, w1ah,
                      __hfma2(xb2, w1bh, __hmul2(xc2, w1ch)));
                h02 = __hmax2(__hfma2(z02, s1h, t1h), hz);
                *(__half2*)(smc + SB_H + rb * 128 + ((c4 ^ (rb & 7)) << 4) + lo)
                    = h02;
            }
            #pragma unroll
            for (int f = 0; f < 5; ++f) {
                __half2 zp2 = z02, hp2 = h02;
                #pragma unroll
                for (int i = 0; i < 4; ++i) {
                    const int n = 1 + 4 * f + i;
                    const __half2 cph = (i == 0) ? hR2 : h05;
                    uint4 xq = *(const uint4*)(px + 4 * n);
                    __half2 xa2 = *(__half2*)&xq.x;
                    __half2 xb2 = *(__half2*)&xq.y;
                    __half2 xc2 = *(__half2*)&xq.z;
                    __half2 zn2 = __hfma2(xa2, w1ah,
                                  __hfma2(xb2, w1bh, __hmul2(xc2, w1ch)));
                    __half2 m12 = __hfma2(zn2, h05, __hmul2(zp2, cph));
                    __half2 hn2 = __hmax2(__hfma2(m12, s1h, t1h), hz);
                    __half2 m22 = __hfma2(hn2, h05, __hmul2(hp2, cph));
                    const int row = rb + n;
                    *(__half2*)(smc + SB_H + row * 128
                                + ((c4 ^ (row & 7)) << 4) + lo) = m22;
                    zp2 = zn2; hp2 = hn2;
                }
            }
        }
        __syncthreads();                              // BAR1: H ready

        // ---- phase 2: MMA + MMA pooling + fused MMA layer-3 ---------------
        {
            float vC[2][4];
            #pragma unroll
            for (int mt = 0; mt < 2; ++mt)
                #pragma unroll
                for (int q = 0; q < 4; ++q) vC[mt][q] = 0.f;

            #pragma unroll
            for (int nt = 0; nt < 12; ++nt) {
                float acc[8] = {0.f,0.f,0.f,0.f,0.f,0.f,0.f,0.f};
                unsigned b[8];
                ldsm4(b[0], b[1], b[2], b[3], bB[0] + nt * 1024);
                ldsm4(b[4], b[5], b[6], b[7], bB[1] + nt * 1024);
                #pragma unroll
                for (int kk = 0; kk < 4; ++kk) {
                    mma16816(acc,     ah[kk][0], b[2 * kk], b[2 * kk + 1]);
                    mma16816(acc + 4, ah[kk][1], b[2 * kk], b[2 * kk + 1]);
                }
                unsigned bp;
                ldsm1(bp, bpAddr + nt * 128);
                #pragma unroll
                for (int mt = 0; mt < 2; ++mt) {
                    unsigned pa0 = relupack2(acc[4 * mt], acc[4 * mt + 1],
                                             t2h[2 * mt]);
                    unsigned pa1 = relupack2(acc[4 * mt + 2], acc[4 * mt + 3],
                                             t2h[2 * mt + 1]);
                    mma16808(vC[mt], pa0, pa1, bp);
                }
            }

            // transpose vC (j x g) -> B-fragment (k=j, n=g) via movmatrix
            unsigned bT[2][2];
            #pragma unroll
            for (int mt = 0; mt < 2; ++mt) {
                __half2 p0 = __floats2half2_rn(vC[mt][0], vC[mt][1]);
                __half2 p1 = __floats2half2_rn(vC[mt][2], vC[mt][3]);
                bT[mt][0] = movm(*(unsigned*)&p0);    // j block lower 8
                bT[mt][1] = movm(*(unsigned*)&p1);    // j block upper 8
            }
            // layer-3 MMA: k = own 32 j's, A = W3^T/21 fragments from smem
            float yc[8] = {0.f,0.f,0.f,0.f,0.f,0.f,0.f,0.f};
            #pragma unroll
            for (int ks = 0; ks < 2; ++ks) {
                uint4 aw0 = *(const uint4*)(smc + SB_W3F
                            + ((jq * 2 + ks) * 2 + 0) * 512 + lane * 16);
                mma16816(yc, (const unsigned*)&aw0, bT[ks][0], bT[ks][1]);
                uint4 aw1 = *(const uint4*)(smc + SB_W3F
                            + ((jq * 2 + ks) * 2 + 1) * 512 + lane * 16);
                mma16816(yc + 4, (const unsigned*)&aw1, bT[ks][0], bT[ks][1]);
            }
            // store partial y: [jq][half][gl][32 c]; valid g-slots at lc<2
            if (lc < 2) {
                float* py = smf + SB_PY / 4 + ((jq * 2 + half) * 4) * 32;
                #pragma unroll
                for (int mt = 0; mt < 2; ++mt) {
                    py[(2 * lc)     * 32 + 16 * mt + lr]     = yc[4 * mt];
                    py[(2 * lc + 1) * 32 + 16 * mt + lr]     = yc[4 * mt + 1];
                    py[(2 * lc)     * 32 + 16 * mt + lr + 8] = yc[4 * mt + 2];
                    py[(2 * lc + 1) * 32 + 16 * mt + lr + 8] = yc[4 * mt + 3];
                }
            }
        }
        __syncthreads();                              // BAR2: PY ready

        // ---- phase 5: combine + log_softmax (warp = graph) ----------------
        {
            float yy = smf[SB_PY / 4 + (0 * 2 + half) * 128 + (wid & 3) * 32 + lane]
                     + smf[SB_PY / 4 + (1 * 2 + half) * 128 + (wid & 3) * 32 + lane]
                     + smf[SB_PY / 4 + (2 * 2 + half) * 128 + (wid & 3) * 32 + lane]
                     + smf[SB_PY / 4 + (3 * 2 + half) * 128 + (wid & 3) * 32 + lane];
            float logit = (lane < NCLS) ? yy + smf[SB_B3 / 4 + lane] : -1e30f;
            float mx = logit;
            #pragma unroll
            for (int o = 16; o; o >>= 1)
                mx = fmaxf(mx, __shfl_xor_sync(0xffffffffu, mx, o));
            float e = (lane < NCLS) ? __expf(logit - mx) : 0.f;
            float s = e;
            #pragma unroll
            for (int o = 16; o; o >>= 1)
                s += __shfl_xor_sync(0xffffffffu, s, o);
            if (lane < NCLS)
                out[(size_t)(gbase + wid) * NCLS + lane]
                    = logit - mx - __logf(s);
        }
        // H WAR: next P1 after this BAR2+P5; P5 reads PY before next BAR1,
        // next P2 writes PY after next BAR1 -> ordered.
    }
}

extern "C" void kernel_launch(void* const* d_in, const int* in_sizes, int n_in,
                              void* d_out, int out_size) {
    const float* x   = (const float*)d_in[0];
    const float* W1  = (const float*)d_in[1];
    const float* b1  = (const float*)d_in[2];
    const float* g1  = (const float*)d_in[3];
    const float* be1 = (const float*)d_in[4];
    const float* m1  = (const float*)d_in[5];
    const float* v1  = (const float*)d_in[6];
    const float* W2  = (const float*)d_in[7];
    const float* b2  = (const float*)d_in[8];
    const float* g2  = (const float*)d_in[9];
    const float* be2 = (const float*)d_in[10];
    const float* m2  = (const float*)d_in[11];
    const float* v2  = (const float*)d_in[12];
    const float* W3  = (const float*)d_in[13];
    const float* b3  = (const float*)d_in[14];

    cudaFuncSetAttribute(gcn_r14_kernel,
                         cudaFuncAttributeMaxDynamicSharedMemorySize, SB_TOT);
    gcn_r14_kernel<<<GRID, 256, SB_TOT>>>(
        x, W1, b1, g1, be1, m1, v1,
        W2, b2, g2, be2, m2, v2, W3, b3, (float*)d_out);
}

// round 16
// speedup vs baseline: 1.0887x; 1.0453x over previous
#include <cuda_runtime.h>
#include <cuda_fp16.h>
#include <math.h>

// ---------------------------------------------------------------------------
// Fused 3-layer GCN, fixed 21-node hand skeleton, 50000 graphs.
// R16 = R14 skeleton (identical smem map / addresses) with 21-packed columns:
//   * graphs at 21-row pitch inside the SAME 96-row halves (8 rows slack)
//   * nt loop 12 -> 11 (8.3% of phase-2 MMA/ldsm/pool work deleted)
//   * graph boundaries encoded in the STATIC pool-B matrix (free)
// ---------------------------------------------------------------------------

#define NODES   21
#define NCLS    29
#define NTILES  6250          // 50000 / 8
#define GRID    444           // 148 SM x 3 CTA
#define R2C     0.70710678118654752440f
#define WROOT   4.535533905932737f

// ---- smem byte offsets (identical to R14) ---------------------------------
#define SB_H    0             // h1mix fp16 [192 rows][128B] swizzled  24576
#define SB_A    24576         // W2'*s2 fp16 [128 j][128B] swizzled    16384
#define SB_BP   40960         // pool B [12 slots][8 n][8 k] fp16      1536
#define SB_W3F  42496         // W3^T/21 frag order [4 jq][2 ks][2 mt][32][16B]
#define SB_PY   50688         // partial y [4 jq][2 half][4 gl][32] f32 4096
#define SB_X    54784         // x staged dup-half2 [8 w][21][4]       2688
#define SB_T2   57472         // 128 f32
#define SB_B3   57984         // 32 f32
#define SB_C    58112         // W1 half2 col-pairs [3][32]            384(+pad)
#define SB_S1   58880         // s1 half2 [32]                         128
#define SB_T1   59008         // t1 half2 [32]                         128
#define SB_TOT  59136         // x3 CTA = 177,408

// ---- PTX helpers ----------------------------------------------------------
__device__ __forceinline__ unsigned smem_u32(const void* p) {
    unsigned a;
    asm("{ .reg .u64 t; cvta.to.shared.u64 t, %1; cvt.u32.u64 %0, t; }"
        : "=r"(a) : "l"(p));
    return a;
}
__device__ __forceinline__ void ldsm4(unsigned& r0, unsigned& r1,
                                      unsigned& r2, unsigned& r3, unsigned a) {
    asm volatile("ldmatrix.sync.aligned.m8n8.x4.shared.b16 {%0,%1,%2,%3}, [%4];"
                 : "=r"(r0), "=r"(r1), "=r"(r2), "=r"(r3) : "r"(a));
}
__device__ __forceinline__ void ldsm1(unsigned& r0, unsigned a) {
    asm volatile("ldmatrix.sync.aligned.m8n8.x1.shared.b16 {%0}, [%1];"
                 : "=r"(r0) : "r"(a));
}
__device__ __forceinline__ unsigned movm(unsigned a) {
    unsigned d;
    asm volatile("movmatrix.sync.aligned.m8n8.trans.b16 %0, %1;"
                 : "=r"(d) : "r"(a));
    return d;
}
__device__ __forceinline__ void mma16816(float* c, const unsigned* a,
                                         unsigned b0, unsigned b1) {
    asm volatile(
        "mma.sync.aligned.m16n8k16.row.col.f32.f16.f16.f32 "
        "{%0,%1,%2,%3}, {%4,%5,%6,%7}, {%8,%9}, {%0,%1,%2,%3};"
        : "+f"(c[0]), "+f"(c[1]), "+f"(c[2]), "+f"(c[3])
        : "r"(a[0]), "r"(a[1]), "r"(a[2]), "r"(a[3]), "r"(b0), "r"(b1));
}
__device__ __forceinline__ void mma16808(float* c, unsigned a0, unsigned a1,
                                         unsigned b0) {
    asm volatile(
        "mma.sync.aligned.m16n8k8.row.col.f32.f16.f16.f32 "
        "{%0,%1,%2,%3}, {%4,%5}, {%6}, {%0,%1,%2,%3};"
        : "+f"(c[0]), "+f"(c[1]), "+f"(c[2]), "+f"(c[3])
        : "r"(a0), "r"(a1), "r"(b0));
}
__device__ __forceinline__ unsigned relupack2(float a, float b, __half2 t) {
    __half2 h = __floats2half2_rn(a, b);
    h = __hmax2(__hadd2(h, t), __float2half2_rn(0.f));
    return *(unsigned*)&h;
}
__device__ __forceinline__ float wraw21(int l) {    // node weight, l in 0..20
    if (l == 0) return WROOT;
    return ((l & 3) == 0) ? 0.5f : 1.0f;            // leaves 4,8,12,16,20
}

// ---------------------------------------------------------------------------
__global__ void __launch_bounds__(256, 3)
gcn_r16_kernel(const float* __restrict__ x,
               const float* __restrict__ W1, const float* __restrict__ b1,
               const float* __restrict__ g1, const float* __restrict__ be1,
               const float* __restrict__ m1, const float* __restrict__ v1,
               const float* __restrict__ W2, const float* __restrict__ b2,
               const float* __restrict__ g2, const float* __restrict__ be2,
               const float* __restrict__ m2, const float* __restrict__ v2,
               const float* __restrict__ W3, const float* __restrict__ b3,
               float* __restrict__ out) {
    extern __shared__ char smc[];
    float* smf = (float*)smc;
    const unsigned sb = smem_u32(smc);
    const int tid  = threadIdx.x;
    const int lane = tid & 31;
    const int wid  = tid >> 5;          // 0..7
    const int jq   = wid & 3;           // j-strip of 32
    const int half = wid >> 2;          // 0: graphs 0-3, 1: graphs 4-7
    const int lr   = lane >> 2;         // fragment row
    const int lc   = lane & 3;          // fragment col-pair

    // ---------------- staging (once per CTA) -------------------------------
    for (int i = tid; i < 8192; i += 256) {          // A = W2^T*diag(s2), swz
        int j = i & 127, k = i >> 7;
        float s = g2[j] * rsqrtf(v2[j] + 1e-5f);
        int off = SB_A + j * 128 + (((k >> 3) ^ (j & 7)) << 4) + (k & 7) * 2;
        *(__half*)(smc + off) = __float2half(W2[k * 128 + j] * s);
    }
    for (int i = tid; i < 704; i += 256) {           // pool B [11 nt][n][k]
        int nt = i >> 6, n = (i >> 3) & 7, k = i & 7;
        int col = 8 * nt + k;                        // 0..87 within half
        int gl2 = col / 21, ln = col - 21 * gl2;     // graph-local mapping
        float v_ = (gl2 < 4 && n == gl2) ? wraw21(ln) : 0.f;
        *(__half*)(smc + SB_BP + nt * 128 + n * 16 + k * 2) = __float2half(v_);
    }
    // W3^T/21 in A-fragment order: [jq][ks][mt][lane][q] half2
    for (int i = tid; i < 4096; i += 256) {
        int q   = i & 3;
        int ln  = (i >> 2) & 31;
        int mt  = (i >> 7) & 1;
        int ks  = (i >> 8) & 1;
        int jq_ = (i >> 9) & 3;
        int lr_ = ln >> 2, lc_ = ln & 3;
        int cls = 16 * mt + lr_ + 8 * (q & 1);
        int jj  = 32 * jq_ + 16 * ks + 2 * lc_ + 8 * (q >> 1);
        float f0 = (cls < NCLS) ? W3[jj * NCLS + cls] / 21.f : 0.f;
        float f1 = (cls < NCLS) ? W3[(jj + 1) * NCLS + cls] / 21.f : 0.f;
        ((__half2*)(smc + SB_W3F))[i] = __floats2half2_rn(f0, f1);
    }
    for (int i = tid; i < 768; i += 256) {           // zero H pad rows
        int b = i / 384, rem = i - 384 * b;          // 12 rows x 32 floats
        int row = 96 * b + 84 + rem / 32;            // rows 84-95 / 180-191
        *(float*)(smc + SB_H + row * 128 + (rem & 31) * 4) = 0.f;
    }
    if (tid < 128) {
        float s = g2[tid] * rsqrtf(v2[tid] + 1e-5f);
        smf[SB_T2 / 4 + tid] = (b2[tid] - m2[tid]) * s + be2[tid];
    }
    if (tid < NCLS) smf[SB_B3 / 4 + tid] = b3[tid];
    if (tid < 32) {                                  // W1 col-pair half2 [3][32]
        int c2 = 2 * tid;
        ((__half2*)(smc + SB_C))[tid]      = __floats2half2_rn(W1[c2],       W1[c2 + 1]);
        ((__half2*)(smc + SB_C))[32 + tid] = __floats2half2_rn(W1[64 + c2],  W1[65 + c2]);
        ((__half2*)(smc + SB_C))[64 + tid] = __floats2half2_rn(W1[128 + c2], W1[129 + c2]);
    }
    if (tid < 32) {                                  // s1/t1 as half2 pairs
        int c2 = 2 * tid;
        float sa = g1[c2] * rsqrtf(v1[c2] + 1e-5f);
        float sbv = g1[c2 + 1] * rsqrtf(v1[c2 + 1] + 1e-5f);
        float ta = (b1[c2] - m1[c2]) * sa + be1[c2];
        float tb = (b1[c2 + 1] - m1[c2 + 1]) * sbv + be1[c2 + 1];
        ((__half2*)(smc + SB_S1))[tid] = __floats2half2_rn(sa, sbv);
        ((__half2*)(smc + SB_T1))[tid] = __floats2half2_rn(ta, tb);
    }
    __syncthreads();

    // ---- per-warp invariants ---------------------------------------------
    __half2 t2h[4];
    #pragma unroll
    for (int r = 0; r < 4; ++r)
        t2h[r] = __float2half2_rn(smf[SB_T2 / 4 + 32 * jq + lr + 8 * r]);
    unsigned bB[2];
    #pragma unroll
    for (int c = 0; c < 2; ++c)
        bB[c] = sb + SB_H + (96 * half + (lane & 7)) * 128
              + ((((lane >> 3) + 4 * c) ^ (lane & 7)) << 4);
    const unsigned bpAddr = sb + SB_BP + (lane & 7) * 16;
    __half2* const px = (__half2*)(smc + SB_X) + wid * 84;  // [21][4] dup x

    // main-GEMM A fragments (static W2 strip): load ONCE (32 regs)
    unsigned ah[4][2][4];
    #pragma unroll
    for (int kk = 0; kk < 4; ++kk)
        #pragma unroll
        for (int mt = 0; mt < 2; ++mt) {
            int row = 32 * jq + 16 * mt + (lane & 15);
            ldsm4(ah[kk][mt][0], ah[kk][mt][1], ah[kk][mt][2], ah[kk][mt][3],
                  sb + SB_A + row * 128
                  + ((((lane >> 4) + 2 * kk) ^ (row & 7)) << 4));
        }

    for (int tile = blockIdx.x; tile < NTILES; tile += GRID) {
        const int gbase = tile * 8;

        // ---- phase 1: layer 1 + mix + BN + ReLU + mix2 -> H (warp=graph) --
        {
            const __half2 w1ah = ((const __half2*)(smc + SB_C))[lane];
            const __half2 w1bh = ((const __half2*)(smc + SB_C))[32 + lane];
            const __half2 w1ch = ((const __half2*)(smc + SB_C))[64 + lane];
            const __half2 s1h = ((const __half2*)(smc + SB_S1))[lane];
            const __half2 t1h = ((const __half2*)(smc + SB_T1))[lane];
            const __half2 h05 = __float2half2_rn(0.5f);
            const __half2 hR2 = __float2half2_rn(R2C);
            const __half2 hz  = __float2half2_rn(0.f);
            const float* xg = x + (size_t)(gbase + wid) * 63;

            // stage x as duplicated half2 into per-warp padded buffer
            {
                float xa0 = xg[lane];
                px[(lane / 3) * 4 + lane % 3]
                    = __half2half2(__float2half(xa0));
                if (lane < 31) {
                    float xa1 = xg[32 + lane];
                    int p1 = 32 + lane;
                    px[(p1 / 3) * 4 + p1 % 3]
                        = __half2half2(__float2half(xa1));
                }
            }
            __syncwarp();

            const int rb = 96 * half + 21 * jq;      // 21-row pitch
            const int c4 = lane >> 2;
            const int lo = (lane & 3) * 4;

            __half2 z02, h02;
            {
                uint4 xq = *(const uint4*)(px);
                __half2 xa2 = *(__half2*)&xq.x;
                __half2 xb2 = *(__half2*)&xq.y;
                __half2 xc2 = *(__half2*)&xq.z;
                z02 = __hfma2(xa2, w1ah,
                      __hfma2(xb2, w1bh, __hmul2(xc2, w1ch)));
                h02 = __hmax2(__hfma2(z02, s1h, t1h), hz);
                *(__half2*)(smc + SB_H + rb * 128 + ((c4 ^ (rb & 7)) << 4) + lo)
                    = h02;
            }
            #pragma unroll
            for (int f = 0; f < 5; ++f) {
                __half2 zp2 = z02, hp2 = h02;
                #pragma unroll
                for (int i = 0; i < 4; ++i) {
                    const int n = 1 + 4 * f + i;
                    const __half2 cph = (i == 0) ? hR2 : h05;
                    uint4 xq = *(const uint4*)(px + 4 * n);
                    __half2 xa2 = *(__half2*)&xq.x;
                    __half2 xb2 = *(__half2*)&xq.y;
                    __half2 xc2 = *(__half2*)&xq.z;
                    __half2 zn2 = __hfma2(xa2, w1ah,
                                  __hfma2(xb2, w1bh, __hmul2(xc2, w1ch)));
                    __half2 m12 = __hfma2(zn2, h05, __hmul2(zp2, cph));
                    __half2 hn2 = __hmax2(__hfma2(m12, s1h, t1h), hz);
                    __half2 m22 = __hfma2(hn2, h05, __hmul2(hp2, cph));
                    const int row = rb + n;
                    *(__half2*)(smc + SB_H + row * 128
                                + ((c4 ^ (row & 7)) << 4) + lo) = m22;
                    zp2 = zn2; hp2 = hn2;
                }
            }
        }
        __syncthreads();                              // BAR1: H ready

        // ---- phase 2: MMA (11 nt) + MMA pooling + fused MMA layer-3 -------
        {
            float vC[2][4];
            #pragma unroll
            for (int mt = 0; mt < 2; ++mt)
                #pragma unroll
                for (int q = 0; q < 4; ++q) vC[mt][q] = 0.f;

            #pragma unroll
            for (int nt = 0; nt < 11; ++nt) {
                float acc[8] = {0.f,0.f,0.f,0.f,0.f,0.f,0.f,0.f};
                unsigned b[8];
                ldsm4(b[0], b[1], b[2], b[3], bB[0] + nt * 1024);
                ldsm4(b[4], b[5], b[6], b[7], bB[1] + nt * 1024);
                #pragma unroll
                for (int kk = 0; kk < 4; ++kk) {
                    mma16816(acc,     ah[kk][0], b[2 * kk], b[2 * kk + 1]);
                    mma16816(acc + 4, ah[kk][1], b[2 * kk], b[2 * kk + 1]);
                }
                unsigned bp;
                ldsm1(bp, bpAddr + nt * 128);
                #pragma unroll
                for (int mt = 0; mt < 2; ++mt) {
                    unsigned pa0 = relupack2(acc[4 * mt], acc[4 * mt + 1],
                                             t2h[2 * mt]);
                    unsigned pa1 = relupack2(acc[4 * mt + 2], acc[4 * mt + 3],
                                             t2h[2 * mt + 1]);
                    mma16808(vC[mt], pa0, pa1, bp);
                }
            }

            // transpose vC (j x g) -> B-fragment (k=j, n=g) via movmatrix
            unsigned bT[2][2];
            #pragma unroll
            for (int mt = 0; mt < 2; ++mt) {
                __half2 p0 = __floats2half2_rn(vC[mt][0], vC[mt][1]);
                __half2 p1 = __floats2half2_rn(vC[mt][2], vC[mt][3]);
                bT[mt][0] = movm(*(unsigned*)&p0);    // j block lower 8
                bT[mt][1] = movm(*(unsigned*)&p1);    // j block upper 8
            }
            // layer-3 MMA: k = own 32 j's, A = W3^T/21 fragments from smem
            float yc[8] = {0.f,0.f,0.f,0.f,0.f,0.f,0.f,0.f};
            #pragma unroll
            for (int ks = 0; ks < 2; ++ks) {
                uint4 aw0 = *(const uint4*)(smc + SB_W3F
                            + ((jq * 2 + ks) * 2 + 0) * 512 + lane * 16);
                mma16816(yc, (const unsigned*)&aw0, bT[ks][0], bT[ks][1]);
                uint4 aw1 = *(const uint4*)(smc + SB_W3F
                            + ((jq * 2 + ks) * 2 + 1) * 512 + lane * 16);
                mma16816(yc + 4, (const unsigned*)&aw1, bT[ks][0], bT[ks][1]);
            }
            // store partial y: [jq][half][gl][32 c]; valid g-slots at lc<2
            if (lc < 2) {
                float* py = smf + SB_PY / 4 + ((jq * 2 + half) * 4) * 32;
                #pragma unroll
                for (int mt = 0; mt < 2; ++mt) {
                    py[(2 * lc)     * 32 + 16 * mt + lr]     = yc[4 * mt];
                    py[(2 * lc + 1) * 32 + 16 * mt + lr]     = yc[4 * mt + 1];
                    py[(2 * lc)     * 32 + 16 * mt + lr + 8] = yc[4 * mt + 2];
                    py[(2 * lc + 1) * 32 + 16 * mt + lr + 8] = yc[4 * mt + 3];
                }
            }
        }
        __syncthreads();                              // BAR2: PY ready

        // ---- phase 5: combine + log_softmax (warp = graph) ----------------
        {
            float yy = smf[SB_PY / 4 + (0 * 2 + half) * 128 + (wid & 3) * 32 + lane]
                     + smf[SB_PY / 4 + (1 * 2 + half) * 128 + (wid & 3) * 32 + lane]
                     + smf[SB_PY / 4 + (2 * 2 + half) * 128 + (wid & 3) * 32 + lane]
                     + smf[SB_PY / 4 + (3 * 2 + half) * 128 + (wid & 3) * 32 + lane];
            float logit = (lane < NCLS) ? yy + smf[SB_B3 / 4 + lane] : -1e30f;
            float mx = logit;
            #pragma unroll
            for (int o = 16; o; o >>= 1)
                mx = fmaxf(mx, __shfl_xor_sync(0xffffffffu, mx, o));
            float e = (lane < NCLS) ? __expf(logit - mx) : 0.f;
            float s = e;
            #pragma unroll
            for (int o = 16; o; o >>= 1)
                s += __shfl_xor_sync(0xffffffffu, s, o);
            if (lane < NCLS)
                out[(size_t)(gbase + wid) * NCLS + lane]
                    = logit - mx - __logf(s);
        }
        // H WAR: next P1 after this BAR2+P5; P5 reads PY before next BAR1,
        // next P2 writes PY after next BAR1 -> ordered.
    }
}

extern "C" void kernel_launch(void* const* d_in, const int* in_sizes, int n_in,
                              void* d_out, int out_size) {
    const float* x   = (const float*)d_in[0];
    const float* W1  = (const float*)d_in[1];
    const float* b1  = (const float*)d_in[2];
    const float* g1  = (const float*)d_in[3];
    const float* be1 = (const float*)d_in[4];
    const float* m1  = (const float*)d_in[5];
    const float* v1  = (const float*)d_in[6];
    const float* W2  = (const float*)d_in[7];
    const float* b2  = (const float*)d_in[8];
    const float* g2  = (const float*)d_in[9];
    const float* be2 = (const float*)d_in[10];
    const float* m2  = (const float*)d_in[11];
    const float* v2  = (const float*)d_in[12];
    const float* W3  = (const float*)d_in[13];
    const float* b3  = (const float*)d_in[14];

    cudaFuncSetAttribute(gcn_r16_kernel,
                         cudaFuncAttributeMaxDynamicSharedMemorySize, SB_TOT);
    gcn_r16_kernel<<<GRID, 256, SB_TOT>>>(
        x, W1, b1, g1, be1, m1, v1,
        W2, b2, g2, be2, m2, v2, W3, b3, (float*)d_out);
}

// round 17
// speedup vs baseline: 1.1161x; 1.0252x over previous
#include <cuda_runtime.h>
#include <cuda_fp16.h>
#include <math.h>

// ---------------------------------------------------------------------------
// Fused 3-layer GCN, fixed 21-node hand skeleton, 50000 graphs.
// R17 = R16 with fp16 MMA accumulators + hoists:
//   * main GEMM and pooling MMAs use f16 C/D: the f16 C-fragment IS the
//     packed layout relupack2 was building -> 48 cvts/tile deleted, and
//     movmatrix consumes the pooling C regs directly.
//   * 11 static pool-B fragments hoisted to registers (ldsm1 once/kernel).
//   * x prefetched into registers during phase 2 (bounds-verified).
// ---------------------------------------------------------------------------

#define NODES   21
#define NCLS    29
#define NTILES  6250          // 50000 / 8
#define GRID    444           // 148 SM x 3 CTA
#define R2C     0.70710678118654752440f
#define WROOT   4.535533905932737f

// ---- smem byte offsets (identical to R16) ---------------------------------
#define SB_H    0             // h1mix fp16 [192 rows][128B] swizzled  24576
#define SB_A    24576         // W2'*s2 fp16 [128 j][128B] swizzled    16384
#define SB_BP   40960         // pool B [12 slots][8 n][8 k] fp16      1536
#define SB_W3F  42496         // W3^T/21 frag order [4 jq][2 ks][2 mt][32][16B]
#define SB_PY   50688         // partial y [4 jq][2 half][4 gl][32] f32 4096
#define SB_X    54784         // x staged dup-half2 [8 w][21][4]       2688
#define SB_T2   57472         // 128 f32
#define SB_B3   57984         // 32 f32
#define SB_C    58112         // W1 half2 col-pairs [3][32]            384(+pad)
#define SB_S1   58880         // s1 half2 [32]                         128
#define SB_T1   59008         // t1 half2 [32]                         128
#define SB_TOT  59136         // x3 CTA = 177,408

// ---- PTX helpers ----------------------------------------------------------
__device__ __forceinline__ unsigned smem_u32(const void* p) {
    unsigned a;
    asm("{ .reg .u64 t; cvta.to.shared.u64 t, %1; cvt.u32.u64 %0, t; }"
        : "=r"(a) : "l"(p));
    return a;
}
__device__ __forceinline__ void ldsm4(unsigned& r0, unsigned& r1,
                                      unsigned& r2, unsigned& r3, unsigned a) {
    asm volatile("ldmatrix.sync.aligned.m8n8.x4.shared.b16 {%0,%1,%2,%3}, [%4];"
                 : "=r"(r0), "=r"(r1), "=r"(r2), "=r"(r3) : "r"(a));
}
__device__ __forceinline__ void ldsm1(unsigned& r0, unsigned a) {
    asm volatile("ldmatrix.sync.aligned.m8n8.x1.shared.b16 {%0}, [%1];"
                 : "=r"(r0) : "r"(a));
}
__device__ __forceinline__ unsigned movm(unsigned a) {
    unsigned d;
    asm volatile("movmatrix.sync.aligned.m8n8.trans.b16 %0, %1;"
                 : "=r"(d) : "r"(a));
    return d;
}
// f32-accum m16n8k16 (layer 3 only)
__device__ __forceinline__ void mma16816(float* c, const unsigned* a,
                                         unsigned b0, unsigned b1) {
    asm volatile(
        "mma.sync.aligned.m16n8k16.row.col.f32.f16.f16.f32 "
        "{%0,%1,%2,%3}, {%4,%5,%6,%7}, {%8,%9}, {%0,%1,%2,%3};"
        : "+f"(c[0]), "+f"(c[1]), "+f"(c[2]), "+f"(c[3])
        : "r"(a[0]), "r"(a[1]), "r"(a[2]), "r"(a[3]), "r"(b0), "r"(b1));
}
// f16-accum m16n8k16 (main GEMM): C/D = 2 packed half2 regs
__device__ __forceinline__ void mma16816h(unsigned* c, const unsigned* a,
                                          unsigned b0, unsigned b1) {
    asm volatile(
        "mma.sync.aligned.m16n8k16.row.col.f16.f16.f16.f16 "
        "{%0,%1}, {%2,%3,%4,%5}, {%6,%7}, {%0,%1};"
        : "+r"(c[0]), "+r"(c[1])
        : "r"(a[0]), "r"(a[1]), "r"(a[2]), "r"(a[3]), "r"(b0), "r"(b1));
}
// f16-accum m16n8k8 (pooling)
__device__ __forceinline__ void mma16808h(unsigned* c, unsigned a0, unsigned a1,
                                          unsigned b0) {
    asm volatile(
        "mma.sync.aligned.m16n8k8.row.col.f16.f16.f16.f16 "
        "{%0,%1}, {%2,%3}, {%4}, {%0,%1};"
        : "+r"(c[0]), "+r"(c[1])
        : "r"(a0), "r"(a1), "r"(b0));
}
__device__ __forceinline__ float wraw21(int l) {    // node weight, l in 0..20
    if (l == 0) return WROOT;
    return ((l & 3) == 0) ? 0.5f : 1.0f;            // leaves 4,8,12,16,20
}

// ---------------------------------------------------------------------------
__global__ void __launch_bounds__(256, 3)
gcn_r17_kernel(const float* __restrict__ x,
               const float* __restrict__ W1, const float* __restrict__ b1,
               const float* __restrict__ g1, const float* __restrict__ be1,
               const float* __restrict__ m1, const float* __restrict__ v1,
               const float* __restrict__ W2, const float* __restrict__ b2,
               const float* __restrict__ g2, const float* __restrict__ be2,
               const float* __restrict__ m2, const float* __restrict__ v2,
               const float* __restrict__ W3, const float* __restrict__ b3,
               float* __restrict__ out) {
    extern __shared__ char smc[];
    float* smf = (float*)smc;
    const unsigned sb = smem_u32(smc);
    const int tid  = threadIdx.x;
    const int lane = tid & 31;
    const int wid  = tid >> 5;          // 0..7
    const int jq   = wid & 3;           // j-strip of 32
    const int half = wid >> 2;          // 0: graphs 0-3, 1: graphs 4-7
    const int lr   = lane >> 2;         // fragment row
    const int lc   = lane & 3;          // fragment col-pair

    // ---------------- staging (once per CTA) -------------------------------
    for (int i = tid; i < 8192; i += 256) {          // A = W2^T*diag(s2), swz
        int j = i & 127, k = i >> 7;
        float s = g2[j] * rsqrtf(v2[j] + 1e-5f);
        int off = SB_A + j * 128 + (((k >> 3) ^ (j & 7)) << 4) + (k & 7) * 2;
        *(__half*)(smc + off) = __float2half(W2[k * 128 + j] * s);
    }
    for (int i = tid; i < 704; i += 256) {           // pool B [11 nt][n][k]
        int nt = i >> 6, n = (i >> 3) & 7, k = i & 7;
        int col = 8 * nt + k;                        // 0..87 within half
        int gl2 = col / 21, ln = col - 21 * gl2;     // graph-local mapping
        float v_ = (gl2 < 4 && n == gl2) ? wraw21(ln) : 0.f;
        *(__half*)(smc + SB_BP + nt * 128 + n * 16 + k * 2) = __float2half(v_);
    }
    // W3^T/21 in A-fragment order: [jq][ks][mt][lane][q] half2
    for (int i = tid; i < 4096; i += 256) {
        int q   = i & 3;
        int ln  = (i >> 2) & 31;
        int mt  = (i >> 7) & 1;
        int ks  = (i >> 8) & 1;
        int jq_ = (i >> 9) & 3;
        int lr_ = ln >> 2, lc_ = ln & 3;
        int cls = 16 * mt + lr_ + 8 * (q & 1);
        int jj  = 32 * jq_ + 16 * ks + 2 * lc_ + 8 * (q >> 1);
        float f0 = (cls < NCLS) ? W3[jj * NCLS + cls] / 21.f : 0.f;
        float f1 = (cls < NCLS) ? W3[(jj + 1) * NCLS + cls] / 21.f : 0.f;
        ((__half2*)(smc + SB_W3F))[i] = __floats2half2_rn(f0, f1);
    }
    for (int i = tid; i < 768; i += 256) {           // zero H pad rows
        int b = i / 384, rem = i - 384 * b;          // 12 rows x 32 floats
        int row = 96 * b + 84 + rem / 32;            // rows 84-95 / 180-191
        *(float*)(smc + SB_H + row * 128 + (rem & 31) * 4) = 0.f;
    }
    if (tid < 128) {
        float s = g2[tid] * rsqrtf(v2[tid] + 1e-5f);
        smf[SB_T2 / 4 + tid] = (b2[tid] - m2[tid]) * s + be2[tid];
    }
    if (tid < NCLS) smf[SB_B3 / 4 + tid] = b3[tid];
    if (tid < 32) {                                  // W1 col-pair half2 [3][32]
        int c2 = 2 * tid;
        ((__half2*)(smc + SB_C))[tid]      = __floats2half2_rn(W1[c2],       W1[c2 + 1]);
        ((__half2*)(smc + SB_C))[32 + tid] = __floats2half2_rn(W1[64 + c2],  W1[65 + c2]);
        ((__half2*)(smc + SB_C))[64 + tid] = __floats2half2_rn(W1[128 + c2], W1[129 + c2]);
    }
    if (tid < 32) {                                  // s1/t1 as half2 pairs
        int c2 = 2 * tid;
        float sa = g1[c2] * rsqrtf(v1[c2] + 1e-5f);
        float sbv = g1[c2 + 1] * rsqrtf(v1[c2 + 1] + 1e-5f);
        float ta = (b1[c2] - m1[c2]) * sa + be1[c2];
        float tb = (b1[c2 + 1] - m1[c2 + 1]) * sbv + be1[c2 + 1];
        ((__half2*)(smc + SB_S1))[tid] = __floats2half2_rn(sa, sbv);
        ((__half2*)(smc + SB_T1))[tid] = __floats2half2_rn(ta, tb);
    }
    __syncthreads();

    // ---- per-warp invariants ---------------------------------------------
    __half2 t2h[4];
    #pragma unroll
    for (int r = 0; r < 4; ++r)
        t2h[r] = __float2half2_rn(smf[SB_T2 / 4 + 32 * jq + lr + 8 * r]);
    unsigned bB[2];
    #pragma unroll
    for (int c = 0; c < 2; ++c)
        bB[c] = sb + SB_H + (96 * half + (lane & 7)) * 128
              + ((((lane >> 3) + 4 * c) ^ (lane & 7)) << 4);
    __half2* const px = (__half2*)(smc + SB_X) + wid * 84;  // [21][4] dup x

    // main-GEMM A fragments (static W2 strip): load ONCE (32 regs)
    unsigned ah[4][2][4];
    #pragma unroll
    for (int kk = 0; kk < 4; ++kk)
        #pragma unroll
        for (int mt = 0; mt < 2; ++mt) {
            int row = 32 * jq + 16 * mt + (lane & 15);
            ldsm4(ah[kk][mt][0], ah[kk][mt][1], ah[kk][mt][2], ah[kk][mt][3],
                  sb + SB_A + row * 128
                  + ((((lane >> 4) + 2 * kk) ^ (row & 7)) << 4));
        }
    // pool-B fragments (static): load ONCE (11 regs)
    unsigned bpr[11];
    #pragma unroll
    for (int nt = 0; nt < 11; ++nt)
        ldsm1(bpr[nt], sb + SB_BP + (lane & 7) * 16 + nt * 128);

    // ---- x prefetch prologue ---------------------------------------------
    int tile = blockIdx.x;
    float xr0, xr1;
    {
        const float* xg = x + (size_t)(tile * 8 + wid) * 63;
        xr0 = xg[lane];
        xr1 = (lane < 31) ? xg[32 + lane] : 0.f;
    }

    for (; tile < NTILES; tile += GRID) {
        const int gbase = tile * 8;

        // ---- phase 1: layer 1 + mix + BN + ReLU + mix2 -> H (warp=graph) --
        {
            const __half2 w1ah = ((const __half2*)(smc + SB_C))[lane];
            const __half2 w1bh = ((const __half2*)(smc + SB_C))[32 + lane];
            const __half2 w1ch = ((const __half2*)(smc + SB_C))[64 + lane];
            const __half2 s1h = ((const __half2*)(smc + SB_S1))[lane];
            const __half2 t1h = ((const __half2*)(smc + SB_T1))[lane];
            const __half2 h05 = __float2half2_rn(0.5f);
            const __half2 hR2 = __float2half2_rn(R2C);
            const __half2 hz  = __float2half2_rn(0.f);

            // stage prefetched x as duplicated half2 into per-warp buffer
            {
                px[(lane / 3) * 4 + lane % 3]
                    = __half2half2(__float2half(xr0));
                if (lane < 31) {
                    int p1 = 32 + lane;
                    px[(p1 / 3) * 4 + p1 % 3]
                        = __half2half2(__float2half(xr1));
                }
            }
            __syncwarp();

            const int rb = 96 * half + 21 * jq;      // 21-row pitch
            const int c4 = lane >> 2;
            const int lo = (lane & 3) * 4;

            __half2 z02, h02;
            {
                uint4 xq = *(const uint4*)(px);
                __half2 xa2 = *(__half2*)&xq.x;
                __half2 xb2 = *(__half2*)&xq.y;
                __half2 xc2 = *(__half2*)&xq.z;
                z02 = __hfma2(xa2, w1ah,
                      __hfma2(xb2, w1bh, __hmul2(xc2, w1ch)));
                h02 = __hmax2(__hfma2(z02, s1h, t1h), hz);
                *(__half2*)(smc + SB_H + rb * 128 + ((c4 ^ (rb & 7)) << 4) + lo)
                    = h02;
            }
            #pragma unroll
            for (int f = 0; f < 5; ++f) {
                __half2 zp2 = z02, hp2 = h02;
                #pragma unroll
                for (int i = 0; i < 4; ++i) {
                    const int n = 1 + 4 * f + i;
                    const __half2 cph = (i == 0) ? hR2 : h05;
                    uint4 xq = *(const uint4*)(px + 4 * n);
                    __half2 xa2 = *(__half2*)&xq.x;
                    __half2 xb2 = *(__half2*)&xq.y;
                    __half2 xc2 = *(__half2*)&xq.z;
                    __half2 zn2 = __hfma2(xa2, w1ah,
                                  __hfma2(xb2, w1bh, __hmul2(xc2, w1ch)));
                    __half2 m12 = __hfma2(zn2, h05, __hmul2(zp2, cph));
                    __half2 hn2 = __hmax2(__hfma2(m12, s1h, t1h), hz);
                    __half2 m22 = __hfma2(hn2, h05, __hmul2(hp2, cph));
                    const int row = rb + n;
                    *(__half2*)(smc + SB_H + row * 128
                                + ((c4 ^ (row & 7)) << 4) + lo) = m22;
                    zp2 = zn2; hp2 = hn2;
                }
            }
        }
        __syncthreads();                              // BAR1: H ready

        // ---- phase 2: f16 MMA (11 nt) + f16 MMA pooling + MMA layer-3 -----
        {
            const __half2 hz = __float2half2_rn(0.f);
            unsigned vCh[2][2];
            vCh[0][0] = 0u; vCh[0][1] = 0u; vCh[1][0] = 0u; vCh[1][1] = 0u;

            #pragma unroll
            for (int nt = 0; nt < 11; ++nt) {
                unsigned acch[2][2];
                acch[0][0] = 0u; acch[0][1] = 0u;
                acch[1][0] = 0u; acch[1][1] = 0u;
                unsigned b[8];
                ldsm4(b[0], b[1], b[2], b[3], bB[0] + nt * 1024);
                ldsm4(b[4], b[5], b[6], b[7], bB[1] + nt * 1024);
                #pragma unroll
                for (int kk = 0; kk < 4; ++kk) {
                    mma16816h(acch[0], ah[kk][0], b[2 * kk], b[2 * kk + 1]);
                    mma16816h(acch[1], ah[kk][1], b[2 * kk], b[2 * kk + 1]);
                }
                #pragma unroll
                for (int mt = 0; mt < 2; ++mt) {
                    __half2 q0 = __hmax2(__hadd2(*(__half2*)&acch[mt][0],
                                                 t2h[2 * mt]), hz);
                    __half2 q1 = __hmax2(__hadd2(*(__half2*)&acch[mt][1],
                                                 t2h[2 * mt + 1]), hz);
                    mma16808h(vCh[mt], *(unsigned*)&q0, *(unsigned*)&q1,
                              bpr[nt]);
                }
            }

            // prefetch next tile's x (latency covered by rest of phase 2)
            {
                int tn = tile + GRID;
                if (tn < NTILES) {
                    const float* xg2 = x + (size_t)(tn * 8 + wid) * 63;
                    xr0 = xg2[lane];
                    xr1 = (lane < 31) ? xg2[32 + lane] : 0.f;
                }
            }

            // transpose vCh (j x g) -> B-fragment (k=j, n=g) via movmatrix
            unsigned bT[2][2];
            #pragma unroll
            for (int mt = 0; mt < 2; ++mt) {
                bT[mt][0] = movm(vCh[mt][0]);         // j block lower 8
                bT[mt][1] = movm(vCh[mt][1]);         // j block upper 8
            }
            // layer-3 MMA: k = own 32 j's, A = W3^T/21 fragments from smem
            float yc[8] = {0.f,0.f,0.f,0.f,0.f,0.f,0.f,0.f};
            #pragma unroll
            for (int ks = 0; ks < 2; ++ks) {
                uint4 aw0 = *(const uint4*)(smc + SB_W3F
                            + ((jq * 2 + ks) * 2 + 0) * 512 + lane * 16);
                mma16816(yc, (const unsigned*)&aw0, bT[ks][0], bT[ks][1]);
                uint4 aw1 = *(const uint4*)(smc + SB_W3F
                            + ((jq * 2 + ks) * 2 + 1) * 512 + lane * 16);
                mma16816(yc + 4, (const unsigned*)&aw1, bT[ks][0], bT[ks][1]);
            }
            // store partial y: [jq][half][gl][32 c]; valid g-slots at lc<2
            if (lc < 2) {
                float* py = smf + SB_PY / 4 + ((jq * 2 + half) * 4) * 32;
                #pragma unroll
                for (int mt = 0; mt < 2; ++mt) {
                    py[(2 * lc)     * 32 + 16 * mt + lr]     = yc[4 * mt];
                    py[(2 * lc + 1) * 32 + 16 * mt + lr]     = yc[4 * mt + 1];
                    py[(2 * lc)     * 32 + 16 * mt + lr + 8] = yc[4 * mt + 2];
                    py[(2 * lc + 1) * 32 + 16 * mt + lr + 8] = yc[4 * mt + 3];
                }
            }
        }
        __syncthreads();                              // BAR2: PY ready

        // ---- phase 5: combine + log_softmax (warp = graph) ----------------
        {
            float yy = smf[SB_PY / 4 + (0 * 2 + half) * 128 + (wid & 3) * 32 + lane]
                     + smf[SB_PY / 4 + (1 * 2 + half) * 128 + (wid & 3) * 32 + lane]
                     + smf[SB_PY / 4 + (2 * 2 + half) * 128 + (wid & 3) * 32 + lane]
                     + smf[SB_PY / 4 + (3 * 2 + half) * 128 + (wid & 3) * 32 + lane];
            float logit = (lane < NCLS) ? yy + smf[SB_B3 / 4 + lane] : -1e30f;
            float mx = logit;
            #pragma unroll
            for (int o = 16; o; o >>= 1)
                mx = fmaxf(mx, __shfl_xor_sync(0xffffffffu, mx, o));
            float e = (lane < NCLS) ? __expf(logit - mx) : 0.f;
            float s = e;
            #pragma unroll
            for (int o = 16; o; o >>= 1)
                s += __shfl_xor_sync(0xffffffffu, s, o);
            if (lane < NCLS)
                out[(size_t)(gbase + wid) * NCLS + lane]
                    = logit - mx - __logf(s);
        }
        // H WAR: next P1 after this BAR2+P5; P5 reads PY before next BAR1,
        // next P2 writes PY after next BAR1 -> ordered.
    }
}

extern "C" void kernel_launch(void* const* d_in, const int* in_sizes, int n_in,
                              void* d_out, int out_size) {
    const float* x   = (const float*)d_in[0];
    const float* W1  = (const float*)d_in[1];
    const float* b1  = (const float*)d_in[2];
    const float* g1  = (const float*)d_in[3];
    const float* be1 = (const float*)d_in[4];
    const float* m1  = (const float*)d_in[5];
    const float* v1  = (const float*)d_in[6];
    const float* W2  = (const float*)d_in[7];
    const float* b2  = (const float*)d_in[8];
    const float* g2  = (const float*)d_in[9];
    const float* be2 = (const float*)d_in[10];
    const float* m2  = (const float*)d_in[11];
    const float* v2  = (const float*)d_in[12];
    const float* W3  = (const float*)d_in[13];
    const float* b3  = (const float*)d_in[14];

    cudaFuncSetAttribute(gcn_r17_kernel,
                         cudaFuncAttributeMaxDynamicSharedMemorySize, SB_TOT);
    gcn_r17_kernel<<<GRID, 256, SB_TOT>>>(
        x, W1, b1, g1, be1, m1, v1,
        W2, b2, g2, be2, m2, v2, W3, b3, (float*)d_out);
}